// round 11
// baseline (speedup 1.0000x reference)
#include <cuda_runtime.h>
#include <cstdint>

// ---------------------------------------------------------------------------
// Coo2Cel: periodic minimum-image pair displacements within cutoff.
// Inputs: pos_xyz [B,N,3] f32, cel_mat [B,3,3] f32, pbc [B,3] i32, ent [B,N] i32
// Output (single f32 buffer): vec [B,N,N,3] ++ sod [B,N,N] ++ mask [B,N,N]
//
// Stores staged in SMEM (STS.128) and drained by bulk-async (TMA) copies.
// R11: warp-private double-buffered pipelines — zero block-wide barriers.
// Each warp owns a contiguous 2560B slice (vec|sod|mask) per buffer and
// issues its own cp.async.bulk groups with per-warp backpressure.
// ---------------------------------------------------------------------------

#define RC2 36.0f   // rc = 6.0
#define I_TILE 4
#define JBLK 512          // j's per block (128 threads x 4)
#define WJ 128            // j's per warp
#define WARP_FLOATS (WJ * 5)   // 640: vec 384 | sod 128 | mask 128
#define W_SOD (WJ * 3)         // 384
#define W_MSK (WJ * 4)         // 512

// SoA scratch for fractional coordinates (max B*N = 2*4096; padded)
__device__ float g_fx[16384];
__device__ float g_fy[16384];
__device__ float g_fz[16384];

__global__ void frac_kernel(const float* __restrict__ pos,
                            const float* __restrict__ cel,
                            int N, int B)
{
    int idx = blockIdx.x * blockDim.x + threadIdx.x;
    if (idx >= B * N) return;
    int b = idx / N;

    const float* m = cel + b * 9;
    float m00 = m[0], m01 = m[1], m02 = m[2];
    float m10 = m[3], m11 = m[4], m12 = m[5];
    float m20 = m[6], m21 = m[7], m22 = m[8];

    float det = m00 * (m11 * m22 - m12 * m21)
              - m01 * (m10 * m22 - m12 * m20)
              + m02 * (m10 * m21 - m11 * m20);
    float r = 1.0f / det;

    float i00 = (m11 * m22 - m12 * m21) * r;
    float i01 = (m02 * m21 - m01 * m22) * r;
    float i02 = (m01 * m12 - m02 * m11) * r;
    float i10 = (m12 * m20 - m10 * m22) * r;
    float i11 = (m00 * m22 - m02 * m20) * r;
    float i12 = (m02 * m10 - m00 * m12) * r;
    float i20 = (m10 * m21 - m11 * m20) * r;
    float i21 = (m01 * m20 - m00 * m21) * r;
    float i22 = (m00 * m11 - m01 * m10) * r;

    float p0 = pos[idx * 3 + 0];
    float p1 = pos[idx * 3 + 1];
    float p2 = pos[idx * 3 + 2];

    g_fx[idx] = p0 * i00 + p1 * i10 + p2 * i20;
    g_fy[idx] = p0 * i01 + p1 * i11 + p2 * i21;
    g_fz[idx] = p0 * i02 + p1 * i12 + p2 * i22;
}

__device__ __forceinline__ uint32_t smem_u32(const void* p) {
    uint32_t a;
    asm("{ .reg .u64 t; cvta.to.shared.u64 t, %1; cvt.u32.u64 %0, t; }"
        : "=r"(a) : "l"(p));
    return a;
}

__global__ void __launch_bounds__(128)
pair_kernel(const float* __restrict__ cel,
            const int*   __restrict__ pbc,
            const int*   __restrict__ ent,
            float* __restrict__ out,
            int N, int B)
{
    // [buffer][warp][floats] — each warp's slice is contiguous & 16B aligned
    __shared__ __align__(16) float sbuf[2][4][WARP_FLOATS];

    const int b    = blockIdx.z;
    const int i0   = blockIdx.y * I_TILE;
    const int jb   = blockIdx.x * JBLK;
    const int warp = threadIdx.x >> 5;
    const int lane = threadIdx.x & 31;
    const int jwb  = jb + warp * WJ;      // warp's j base
    const int j0   = jwb + lane * 4;

    const float* c = cel + b * 9;
    const float c00 = c[0], c01 = c[1], c02 = c[2];
    const float c10 = c[3], c11 = c[4], c12 = c[5];
    const float c20 = c[6], c21 = c[7], c22 = c[8];

    const float pb0 = pbc[b * 3 + 0] ? 1.0f : 0.0f;
    const float pb1 = pbc[b * 3 + 1] ? 1.0f : 0.0f;
    const float pb2 = pbc[b * 3 + 2] ? 1.0f : 0.0f;

    const int base = b * N;

    // j-side data: loaded ONCE, reused for all I_TILE i's
    const float4 fx4 = *reinterpret_cast<const float4*>(g_fx + base + j0);
    const float4 fy4 = *reinterpret_cast<const float4*>(g_fy + base + j0);
    const float4 fz4 = *reinterpret_cast<const float4*>(g_fz + base + j0);
    const int4   ej4 = *reinterpret_cast<const int4*>(ent + base + j0);

    const float fjx[4] = { fx4.x, fx4.y, fx4.z, fx4.w };
    const float fjy[4] = { fy4.x, fy4.y, fy4.z, fy4.w };
    const float fjz[4] = { fz4.x, fz4.y, fz4.z, fz4.w };
    const bool  ej[4]  = { ej4.x != 0, ej4.y != 0, ej4.z != 0, ej4.w != 0 };

    const size_t NN       = (size_t)N * N;
    const size_t sod_off  = (size_t)B * NN * 3;
    const size_t mask_off = (size_t)B * NN * 4;

    #pragma unroll 1
    for (int t = 0; t < I_TILE; ++t) {
        const int i = i0 + t;
        float* buf = sbuf[t & 1][warp];

        // per-warp backpressure: this buffer's group committed at t-2
        if (t >= 2) {
            if (lane == 0)
                asm volatile("cp.async.bulk.wait_group.read 1;" ::: "memory");
            __syncwarp();
        }

        const float fi0 = g_fx[base + i];
        const float fi1 = g_fy[base + i];
        const float fi2 = g_fz[base + i];
        const bool  ent_i = ent[base + i] != 0;

        float vx[4], vy[4], vz[4], sd[4], mk[4];

        #pragma unroll
        for (int k = 0; k < 4; ++k) {
            const int j = j0 + k;
            float d0 = fjx[k] - fi0;
            float d1 = fjy[k] - fi1;
            float d2 = fjz[k] - fi2;
            d0 -= rintf(d0) * pb0;   // round-half-even, matches jnp.round
            d1 -= rintf(d1) * pb1;
            d2 -= rintf(d2) * pb2;

            float v0 = d0 * c00 + d1 * c10 + d2 * c20;
            float v1 = d0 * c01 + d1 * c11 + d2 * c21;
            float v2 = d0 * c02 + d1 * c12 + d2 * c22;
            float s  = v0 * v0 + v1 * v1 + v2 * v2;

            bool ok = ent_i && ej[k] && (i != j) && (s < RC2);
            vx[k] = ok ? v0 : 0.0f;
            vy[k] = ok ? v1 : 0.0f;
            vz[k] = ok ? v2 : 0.0f;
            sd[k] = ok ? s  : 0.0f;
            mk[k] = ok ? 1.0f : 0.0f;
        }

        // stage into warp-private SMEM slice (STS.128)
        float4* vdst = reinterpret_cast<float4*>(buf + lane * 12);
        vdst[0] = make_float4(vx[0], vy[0], vz[0], vx[1]);
        vdst[1] = make_float4(vy[1], vz[1], vx[2], vy[2]);
        vdst[2] = make_float4(vz[2], vx[3], vy[3], vz[3]);
        *reinterpret_cast<float4*>(buf + W_SOD + lane * 4) =
            make_float4(sd[0], sd[1], sd[2], sd[3]);
        *reinterpret_cast<float4*>(buf + W_MSK + lane * 4) =
            make_float4(mk[0], mk[1], mk[2], mk[3]);

        __syncwarp();

        if (lane == 0) {
            asm volatile("fence.proxy.async.shared::cta;" ::: "memory");
            const size_t pair = ((size_t)base + i) * N + jwb;
            uint32_t s_vec = smem_u32(buf);
            uint32_t s_sod = smem_u32(buf + W_SOD);
            uint32_t s_msk = smem_u32(buf + W_MSK);
            float* g_vec = out + pair * 3;
            float* g_sod = out + sod_off + pair;
            float* g_msk = out + mask_off + pair;

            asm volatile(
                "cp.async.bulk.global.shared::cta.bulk_group [%0], [%1], %2;"
                :: "l"(g_vec), "r"(s_vec), "r"(WJ * 3 * 4) : "memory");
            asm volatile(
                "cp.async.bulk.global.shared::cta.bulk_group [%0], [%1], %2;"
                :: "l"(g_sod), "r"(s_sod), "r"(WJ * 4) : "memory");
            asm volatile(
                "cp.async.bulk.global.shared::cta.bulk_group [%0], [%1], %2;"
                :: "l"(g_msk), "r"(s_msk), "r"(WJ * 4) : "memory");
            asm volatile("cp.async.bulk.commit_group;" ::: "memory");
        }
        __syncwarp();
    }

    // SMEM must stay alive until this warp's TMA reads complete
    if (lane == 0)
        asm volatile("cp.async.bulk.wait_group.read 0;" ::: "memory");
    __syncwarp();
}

extern "C" void kernel_launch(void* const* d_in, const int* in_sizes, int n_in,
                              void* d_out, int out_size)
{
    const float* pos = (const float*)d_in[0];
    const float* cel = (const float*)d_in[1];
    const int*   pbc = (const int*)  d_in[2];
    const int*   ent = (const int*)  d_in[3];
    float* out = (float*)d_out;

    const int B = in_sizes[1] / 9;          // cel_mat has B*9 elements
    const int N = in_sizes[3] / B;          // ent has B*N elements

    {
        int total = B * N;
        int threads = 256;
        int blocks = (total + threads - 1) / threads;
        frac_kernel<<<blocks, threads>>>(pos, cel, N, B);
    }
    {
        dim3 threads(128, 1, 1);
        dim3 blocks(N / JBLK, N / I_TILE, B);
        pair_kernel<<<blocks, threads>>>(cel, pbc, ent, out, N, B);
    }
}

// round 12
// speedup vs baseline: 1.0172x; 1.0172x over previous
#include <cuda_runtime.h>
#include <cstdint>

// ---------------------------------------------------------------------------
// Coo2Cel: periodic minimum-image pair displacements within cutoff.
// Inputs: pos_xyz [B,N,3] f32, cel_mat [B,3,3] f32, pbc [B,3] i32, ent [B,N] i32
// Output (single f32 buffer): vec [B,N,N,3] ++ sod [B,N,N] ++ mask [B,N,N]
//
// Single fused kernel (R12): frac coords recomputed in each block's prologue
// (3x3 inverse + dot products — trivial vs 671MB of stores), removing the
// separate prep kernel launch from the graph. Stores staged in SMEM (STS.128)
// and drained via cp.async.bulk with warp-private double-buffered pipelines
// (zero block-wide barriers) — bypasses the STG.128 issue-cost wall.
// ---------------------------------------------------------------------------

#define RC2 36.0f   // rc = 6.0
#define I_TILE 4
#define JBLK 512          // j's per block (128 threads x 4)
#define WJ 128            // j's per warp
#define WARP_FLOATS (WJ * 5)   // 640: vec 384 | sod 128 | mask 128
#define W_SOD (WJ * 3)         // 384
#define W_MSK (WJ * 4)         // 512

__device__ __forceinline__ uint32_t smem_u32(const void* p) {
    uint32_t a;
    asm("{ .reg .u64 t; cvta.to.shared.u64 t, %1; cvt.u32.u64 %0, t; }"
        : "=r"(a) : "l"(p));
    return a;
}

__global__ void __launch_bounds__(128)
pair_kernel(const float* __restrict__ pos,
            const float* __restrict__ cel,
            const int*   __restrict__ pbc,
            const int*   __restrict__ ent,
            float* __restrict__ out,
            int N, int B)
{
    // [buffer][warp][floats] — each warp's slice is contiguous & 16B aligned
    __shared__ __align__(16) float sbuf[2][4][WARP_FLOATS];

    const int b    = blockIdx.z;
    const int i0   = blockIdx.y * I_TILE;
    const int jb   = blockIdx.x * JBLK;
    const int warp = threadIdx.x >> 5;
    const int lane = threadIdx.x & 31;
    const int jwb  = jb + warp * WJ;      // warp's j base
    const int j0   = jwb + lane * 4;

    // --- cell matrix + inverse (prologue; registers die after use) ---------
    const float* c = cel + b * 9;
    const float c00 = c[0], c01 = c[1], c02 = c[2];
    const float c10 = c[3], c11 = c[4], c12 = c[5];
    const float c20 = c[6], c21 = c[7], c22 = c[8];

    const float det = c00 * (c11 * c22 - c12 * c21)
                    - c01 * (c10 * c22 - c12 * c20)
                    + c02 * (c10 * c21 - c11 * c20);
    const float r = 1.0f / det;
    const float i00 = (c11 * c22 - c12 * c21) * r;
    const float i01 = (c02 * c21 - c01 * c22) * r;
    const float i02 = (c01 * c12 - c02 * c11) * r;
    const float i10 = (c12 * c20 - c10 * c22) * r;
    const float i11 = (c00 * c22 - c02 * c20) * r;
    const float i12 = (c02 * c10 - c00 * c12) * r;
    const float i20 = (c10 * c21 - c11 * c20) * r;
    const float i21 = (c01 * c20 - c00 * c21) * r;
    const float i22 = (c00 * c11 - c01 * c10) * r;

    const float pb0 = pbc[b * 3 + 0] ? 1.0f : 0.0f;
    const float pb1 = pbc[b * 3 + 1] ? 1.0f : 0.0f;
    const float pb2 = pbc[b * 3 + 2] ? 1.0f : 0.0f;

    const int base = b * N;

    // --- j-side fracs: computed ONCE from pos, reused for all I_TILE i's ---
    // pos for 4 consecutive j: 12 contiguous floats, 16B aligned
    const float4* pj4 = reinterpret_cast<const float4*>(pos + ((size_t)base + j0) * 3);
    const float4 pa = pj4[0];
    const float4 pb4 = pj4[1];
    const float4 pc = pj4[2];
    const float pj[12] = { pa.x, pa.y, pa.z, pa.w,
                           pb4.x, pb4.y, pb4.z, pb4.w,
                           pc.x, pc.y, pc.z, pc.w };

    float fjx[4], fjy[4], fjz[4];
    #pragma unroll
    for (int k = 0; k < 4; ++k) {
        const float p0 = pj[k * 3 + 0];
        const float p1 = pj[k * 3 + 1];
        const float p2 = pj[k * 3 + 2];
        fjx[k] = p0 * i00 + p1 * i10 + p2 * i20;
        fjy[k] = p0 * i01 + p1 * i11 + p2 * i21;
        fjz[k] = p0 * i02 + p1 * i12 + p2 * i22;
    }

    const int4 ej4 = *reinterpret_cast<const int4*>(ent + base + j0);
    const bool ej[4] = { ej4.x != 0, ej4.y != 0, ej4.z != 0, ej4.w != 0 };

    const size_t NN       = (size_t)N * N;
    const size_t sod_off  = (size_t)B * NN * 3;
    const size_t mask_off = (size_t)B * NN * 4;

    #pragma unroll 1
    for (int t = 0; t < I_TILE; ++t) {
        const int i = i0 + t;
        float* buf = sbuf[t & 1][warp];

        // per-warp backpressure: this buffer's group committed at t-2
        if (t >= 2) {
            if (lane == 0)
                asm volatile("cp.async.bulk.wait_group.read 1;" ::: "memory");
            __syncwarp();
        }

        // i-side frac: broadcast loads + one mat-vec (cheap)
        const float q0 = pos[((size_t)base + i) * 3 + 0];
        const float q1 = pos[((size_t)base + i) * 3 + 1];
        const float q2 = pos[((size_t)base + i) * 3 + 2];
        const float fi0 = q0 * i00 + q1 * i10 + q2 * i20;
        const float fi1 = q0 * i01 + q1 * i11 + q2 * i21;
        const float fi2 = q0 * i02 + q1 * i12 + q2 * i22;
        const bool  ent_i = ent[base + i] != 0;

        float vx[4], vy[4], vz[4], sd[4], mk[4];

        #pragma unroll
        for (int k = 0; k < 4; ++k) {
            const int j = j0 + k;
            float d0 = fjx[k] - fi0;
            float d1 = fjy[k] - fi1;
            float d2 = fjz[k] - fi2;
            d0 -= rintf(d0) * pb0;   // round-half-even, matches jnp.round
            d1 -= rintf(d1) * pb1;
            d2 -= rintf(d2) * pb2;

            float v0 = d0 * c00 + d1 * c10 + d2 * c20;
            float v1 = d0 * c01 + d1 * c11 + d2 * c21;
            float v2 = d0 * c02 + d1 * c12 + d2 * c22;
            float s  = v0 * v0 + v1 * v1 + v2 * v2;

            bool ok = ent_i && ej[k] && (i != j) && (s < RC2);
            vx[k] = ok ? v0 : 0.0f;
            vy[k] = ok ? v1 : 0.0f;
            vz[k] = ok ? v2 : 0.0f;
            sd[k] = ok ? s  : 0.0f;
            mk[k] = ok ? 1.0f : 0.0f;
        }

        // stage into warp-private SMEM slice (STS.128)
        float4* vdst = reinterpret_cast<float4*>(buf + lane * 12);
        vdst[0] = make_float4(vx[0], vy[0], vz[0], vx[1]);
        vdst[1] = make_float4(vy[1], vz[1], vx[2], vy[2]);
        vdst[2] = make_float4(vz[2], vx[3], vy[3], vz[3]);
        *reinterpret_cast<float4*>(buf + W_SOD + lane * 4) =
            make_float4(sd[0], sd[1], sd[2], sd[3]);
        *reinterpret_cast<float4*>(buf + W_MSK + lane * 4) =
            make_float4(mk[0], mk[1], mk[2], mk[3]);

        __syncwarp();

        if (lane == 0) {
            asm volatile("fence.proxy.async.shared::cta;" ::: "memory");
            const size_t pair = ((size_t)base + i) * N + jwb;
            uint32_t s_vec = smem_u32(buf);
            uint32_t s_sod = smem_u32(buf + W_SOD);
            uint32_t s_msk = smem_u32(buf + W_MSK);
            float* g_vec = out + pair * 3;
            float* g_sod = out + sod_off + pair;
            float* g_msk = out + mask_off + pair;

            asm volatile(
                "cp.async.bulk.global.shared::cta.bulk_group [%0], [%1], %2;"
                :: "l"(g_vec), "r"(s_vec), "r"(WJ * 3 * 4) : "memory");
            asm volatile(
                "cp.async.bulk.global.shared::cta.bulk_group [%0], [%1], %2;"
                :: "l"(g_sod), "r"(s_sod), "r"(WJ * 4) : "memory");
            asm volatile(
                "cp.async.bulk.global.shared::cta.bulk_group [%0], [%1], %2;"
                :: "l"(g_msk), "r"(s_msk), "r"(WJ * 4) : "memory");
            asm volatile("cp.async.bulk.commit_group;" ::: "memory");
        }
        __syncwarp();
    }

    // SMEM must stay alive until this warp's TMA reads complete
    if (lane == 0)
        asm volatile("cp.async.bulk.wait_group.read 0;" ::: "memory");
    __syncwarp();
}

extern "C" void kernel_launch(void* const* d_in, const int* in_sizes, int n_in,
                              void* d_out, int out_size)
{
    const float* pos = (const float*)d_in[0];
    const float* cel = (const float*)d_in[1];
    const int*   pbc = (const int*)  d_in[2];
    const int*   ent = (const int*)  d_in[3];
    float* out = (float*)d_out;

    const int B = in_sizes[1] / 9;          // cel_mat has B*9 elements
    const int N = in_sizes[3] / B;          // ent has B*N elements

    dim3 threads(128, 1, 1);
    dim3 blocks(N / JBLK, N / I_TILE, B);
    pair_kernel<<<blocks, threads>>>(pos, cel, pbc, ent, out, N, B);
}

// round 13
// speedup vs baseline: 1.0224x; 1.0051x over previous
#include <cuda_runtime.h>
#include <cstdint>

// ---------------------------------------------------------------------------
// Coo2Cel: periodic minimum-image pair displacements within cutoff.
// Inputs: pos_xyz [B,N,3] f32, cel_mat [B,3,3] f32, pbc [B,3] i32, ent [B,N] i32
// Output (single f32 buffer): vec [B,N,N,3] ++ sod [B,N,N] ++ mask [B,N,N]
//
// Single fused kernel: frac coords recomputed in each block's prologue,
// stores staged in SMEM (STS.128) and drained via cp.async.bulk with
// warp-private double-buffered pipelines (zero block-wide barriers).
// R13: value-masking via multiply (FMA pipe) instead of selects (ALU pipe)
// to rebalance issue pressure — ALU was at 50%, FMA at 26%.
// ---------------------------------------------------------------------------

#define RC2 36.0f   // rc = 6.0
#define I_TILE 4
#define JBLK 512          // j's per block (128 threads x 4)
#define WJ 128            // j's per warp
#define WARP_FLOATS (WJ * 5)   // 640: vec 384 | sod 128 | mask 128
#define W_SOD (WJ * 3)         // 384
#define W_MSK (WJ * 4)         // 512

__device__ __forceinline__ uint32_t smem_u32(const void* p) {
    uint32_t a;
    asm("{ .reg .u64 t; cvta.to.shared.u64 t, %1; cvt.u32.u64 %0, t; }"
        : "=r"(a) : "l"(p));
    return a;
}

__global__ void __launch_bounds__(128)
pair_kernel(const float* __restrict__ pos,
            const float* __restrict__ cel,
            const int*   __restrict__ pbc,
            const int*   __restrict__ ent,
            float* __restrict__ out,
            int N, int B)
{
    // [buffer][warp][floats] — each warp's slice is contiguous & 16B aligned
    __shared__ __align__(16) float sbuf[2][4][WARP_FLOATS];

    const int b    = blockIdx.z;
    const int i0   = blockIdx.y * I_TILE;
    const int jb   = blockIdx.x * JBLK;
    const int warp = threadIdx.x >> 5;
    const int lane = threadIdx.x & 31;
    const int jwb  = jb + warp * WJ;      // warp's j base
    const int j0   = jwb + lane * 4;

    // --- cell matrix + inverse (prologue; registers die after use) ---------
    const float* c = cel + b * 9;
    const float c00 = c[0], c01 = c[1], c02 = c[2];
    const float c10 = c[3], c11 = c[4], c12 = c[5];
    const float c20 = c[6], c21 = c[7], c22 = c[8];

    const float det = c00 * (c11 * c22 - c12 * c21)
                    - c01 * (c10 * c22 - c12 * c20)
                    + c02 * (c10 * c21 - c11 * c20);
    const float r = 1.0f / det;
    const float i00 = (c11 * c22 - c12 * c21) * r;
    const float i01 = (c02 * c21 - c01 * c22) * r;
    const float i02 = (c01 * c12 - c02 * c11) * r;
    const float i10 = (c12 * c20 - c10 * c22) * r;
    const float i11 = (c00 * c22 - c02 * c20) * r;
    const float i12 = (c02 * c10 - c00 * c12) * r;
    const float i20 = (c10 * c21 - c11 * c20) * r;
    const float i21 = (c01 * c20 - c00 * c21) * r;
    const float i22 = (c00 * c11 - c01 * c10) * r;

    const float pb0 = pbc[b * 3 + 0] ? 1.0f : 0.0f;
    const float pb1 = pbc[b * 3 + 1] ? 1.0f : 0.0f;
    const float pb2 = pbc[b * 3 + 2] ? 1.0f : 0.0f;

    const int base = b * N;

    // --- j-side fracs: computed ONCE from pos, reused for all I_TILE i's ---
    const float4* pj4 = reinterpret_cast<const float4*>(pos + ((size_t)base + j0) * 3);
    const float4 pa = pj4[0];
    const float4 pb4 = pj4[1];
    const float4 pc = pj4[2];
    const float pj[12] = { pa.x, pa.y, pa.z, pa.w,
                           pb4.x, pb4.y, pb4.z, pb4.w,
                           pc.x, pc.y, pc.z, pc.w };

    float fjx[4], fjy[4], fjz[4];
    #pragma unroll
    for (int k = 0; k < 4; ++k) {
        const float p0 = pj[k * 3 + 0];
        const float p1 = pj[k * 3 + 1];
        const float p2 = pj[k * 3 + 2];
        fjx[k] = p0 * i00 + p1 * i10 + p2 * i20;
        fjy[k] = p0 * i01 + p1 * i11 + p2 * i21;
        fjz[k] = p0 * i02 + p1 * i12 + p2 * i22;
    }

    const int4 ej4 = *reinterpret_cast<const int4*>(ent + base + j0);
    const bool ej[4] = { ej4.x != 0, ej4.y != 0, ej4.z != 0, ej4.w != 0 };

    const size_t NN       = (size_t)N * N;
    const size_t sod_off  = (size_t)B * NN * 3;
    const size_t mask_off = (size_t)B * NN * 4;

    #pragma unroll 1
    for (int t = 0; t < I_TILE; ++t) {
        const int i = i0 + t;
        float* buf = sbuf[t & 1][warp];

        // per-warp backpressure: this buffer's group committed at t-2
        if (t >= 2) {
            if (lane == 0)
                asm volatile("cp.async.bulk.wait_group.read 1;" ::: "memory");
            __syncwarp();
        }

        // i-side frac: broadcast loads + one mat-vec (cheap)
        const float q0 = pos[((size_t)base + i) * 3 + 0];
        const float q1 = pos[((size_t)base + i) * 3 + 1];
        const float q2 = pos[((size_t)base + i) * 3 + 2];
        const float fi0 = q0 * i00 + q1 * i10 + q2 * i20;
        const float fi1 = q0 * i01 + q1 * i11 + q2 * i21;
        const float fi2 = q0 * i02 + q1 * i12 + q2 * i22;
        const bool  ent_i = ent[base + i] != 0;

        float vx[4], vy[4], vz[4], sd[4], mk[4];

        #pragma unroll
        for (int k = 0; k < 4; ++k) {
            const int j = j0 + k;
            float d0 = fjx[k] - fi0;
            float d1 = fjy[k] - fi1;
            float d2 = fjz[k] - fi2;
            d0 -= rintf(d0) * pb0;   // round-half-even, matches jnp.round
            d1 -= rintf(d1) * pb1;
            d2 -= rintf(d2) * pb2;

            float v0 = d0 * c00 + d1 * c10 + d2 * c20;
            float v1 = d0 * c01 + d1 * c11 + d2 * c21;
            float v2 = d0 * c02 + d1 * c12 + d2 * c22;
            float s  = v0 * v0 + v1 * v1 + v2 * v2;

            // one select -> mask float; value-masking via FMUL (FMA pipe)
            const bool ok = ent_i && ej[k] && (i != j) && (s < RC2);
            const float m = ok ? 1.0f : 0.0f;   // exact 1.0/0.0
            vx[k] = v0 * m;
            vy[k] = v1 * m;
            vz[k] = v2 * m;
            sd[k] = s  * m;
            mk[k] = m;
        }

        // stage into warp-private SMEM slice (STS.128)
        float4* vdst = reinterpret_cast<float4*>(buf + lane * 12);
        vdst[0] = make_float4(vx[0], vy[0], vz[0], vx[1]);
        vdst[1] = make_float4(vy[1], vz[1], vx[2], vy[2]);
        vdst[2] = make_float4(vz[2], vx[3], vy[3], vz[3]);
        *reinterpret_cast<float4*>(buf + W_SOD + lane * 4) =
            make_float4(sd[0], sd[1], sd[2], sd[3]);
        *reinterpret_cast<float4*>(buf + W_MSK + lane * 4) =
            make_float4(mk[0], mk[1], mk[2], mk[3]);

        __syncwarp();

        if (lane == 0) {
            asm volatile("fence.proxy.async.shared::cta;" ::: "memory");
            const size_t pair = ((size_t)base + i) * N + jwb;
            uint32_t s_vec = smem_u32(buf);
            uint32_t s_sod = smem_u32(buf + W_SOD);
            uint32_t s_msk = smem_u32(buf + W_MSK);
            float* g_vec = out + pair * 3;
            float* g_sod = out + sod_off + pair;
            float* g_msk = out + mask_off + pair;

            asm volatile(
                "cp.async.bulk.global.shared::cta.bulk_group [%0], [%1], %2;"
                :: "l"(g_vec), "r"(s_vec), "r"(WJ * 3 * 4) : "memory");
            asm volatile(
                "cp.async.bulk.global.shared::cta.bulk_group [%0], [%1], %2;"
                :: "l"(g_sod), "r"(s_sod), "r"(WJ * 4) : "memory");
            asm volatile(
                "cp.async.bulk.global.shared::cta.bulk_group [%0], [%1], %2;"
                :: "l"(g_msk), "r"(s_msk), "r"(WJ * 4) : "memory");
            asm volatile("cp.async.bulk.commit_group;" ::: "memory");
        }
        __syncwarp();
    }

    // SMEM must stay alive until this warp's TMA reads complete
    if (lane == 0)
        asm volatile("cp.async.bulk.wait_group.read 0;" ::: "memory");
    __syncwarp();
}

extern "C" void kernel_launch(void* const* d_in, const int* in_sizes, int n_in,
                              void* d_out, int out_size)
{
    const float* pos = (const float*)d_in[0];
    const float* cel = (const float*)d_in[1];
    const int*   pbc = (const int*)  d_in[2];
    const int*   ent = (const int*)  d_in[3];
    float* out = (float*)d_out;

    const int B = in_sizes[1] / 9;          // cel_mat has B*9 elements
    const int N = in_sizes[3] / B;          // ent has B*N elements

    dim3 threads(128, 1, 1);
    dim3 blocks(N / JBLK, N / I_TILE, B);
    pair_kernel<<<blocks, threads>>>(pos, cel, pbc, ent, out, N, B);
}

// round 14
// speedup vs baseline: 1.0397x; 1.0169x over previous
#include <cuda_runtime.h>
#include <cstdint>

// ---------------------------------------------------------------------------
// Coo2Cel: periodic minimum-image pair displacements within cutoff.
// Inputs: pos_xyz [B,N,3] f32, cel_mat [B,3,3] f32, pbc [B,3] i32, ent [B,N] i32
// Output (single f32 buffer): vec [B,N,N,3] ++ sod [B,N,N] ++ mask [B,N,N]
//
// Single fused kernel: frac coords recomputed in each block's prologue,
// stores staged in SMEM (STS.128) and drained via cp.async.bulk with
// warp-private double-buffered pipelines (zero block-wide barriers).
// R14: bulk stores tagged L2::evict_first (write-once data, never re-read).
// ---------------------------------------------------------------------------

#define RC2 36.0f   // rc = 6.0
#define I_TILE 4
#define JBLK 512          // j's per block (128 threads x 4)
#define WJ 128            // j's per warp
#define WARP_FLOATS (WJ * 5)   // 640: vec 384 | sod 128 | mask 128
#define W_SOD (WJ * 3)         // 384
#define W_MSK (WJ * 4)         // 512

__device__ __forceinline__ uint32_t smem_u32(const void* p) {
    uint32_t a;
    asm("{ .reg .u64 t; cvta.to.shared.u64 t, %1; cvt.u32.u64 %0, t; }"
        : "=r"(a) : "l"(p));
    return a;
}

__device__ __forceinline__ void bulk_store_ef(const float* gdst, uint32_t ssrc,
                                              int nbytes, uint64_t policy) {
    asm volatile(
        "cp.async.bulk.global.shared::cta.bulk_group.L2::cache_hint "
        "[%0], [%1], %2, %3;"
        :: "l"(gdst), "r"(ssrc), "r"(nbytes), "l"(policy) : "memory");
}

__global__ void __launch_bounds__(128)
pair_kernel(const float* __restrict__ pos,
            const float* __restrict__ cel,
            const int*   __restrict__ pbc,
            const int*   __restrict__ ent,
            float* __restrict__ out,
            int N, int B)
{
    // [buffer][warp][floats] — each warp's slice is contiguous & 16B aligned
    __shared__ __align__(16) float sbuf[2][4][WARP_FLOATS];

    const int b    = blockIdx.z;
    const int i0   = blockIdx.y * I_TILE;
    const int jb   = blockIdx.x * JBLK;
    const int warp = threadIdx.x >> 5;
    const int lane = threadIdx.x & 31;
    const int jwb  = jb + warp * WJ;      // warp's j base
    const int j0   = jwb + lane * 4;

    // --- cell matrix + inverse (prologue; registers die after use) ---------
    const float* c = cel + b * 9;
    const float c00 = c[0], c01 = c[1], c02 = c[2];
    const float c10 = c[3], c11 = c[4], c12 = c[5];
    const float c20 = c[6], c21 = c[7], c22 = c[8];

    const float det = c00 * (c11 * c22 - c12 * c21)
                    - c01 * (c10 * c22 - c12 * c20)
                    + c02 * (c10 * c21 - c11 * c20);
    const float r = 1.0f / det;
    const float i00 = (c11 * c22 - c12 * c21) * r;
    const float i01 = (c02 * c21 - c01 * c22) * r;
    const float i02 = (c01 * c12 - c02 * c11) * r;
    const float i10 = (c12 * c20 - c10 * c22) * r;
    const float i11 = (c00 * c22 - c02 * c20) * r;
    const float i12 = (c02 * c10 - c00 * c12) * r;
    const float i20 = (c10 * c21 - c11 * c20) * r;
    const float i21 = (c01 * c20 - c00 * c21) * r;
    const float i22 = (c00 * c11 - c01 * c10) * r;

    const float pb0 = pbc[b * 3 + 0] ? 1.0f : 0.0f;
    const float pb1 = pbc[b * 3 + 1] ? 1.0f : 0.0f;
    const float pb2 = pbc[b * 3 + 2] ? 1.0f : 0.0f;

    // evict_first policy for write-once output
    uint64_t policy;
    asm("createpolicy.fractional.L2::evict_first.b64 %0, 1.0;" : "=l"(policy));

    const int base = b * N;

    // --- j-side fracs: computed ONCE from pos, reused for all I_TILE i's ---
    const float4* pj4 = reinterpret_cast<const float4*>(pos + ((size_t)base + j0) * 3);
    const float4 pa = pj4[0];
    const float4 pb4 = pj4[1];
    const float4 pc = pj4[2];
    const float pj[12] = { pa.x, pa.y, pa.z, pa.w,
                           pb4.x, pb4.y, pb4.z, pb4.w,
                           pc.x, pc.y, pc.z, pc.w };

    float fjx[4], fjy[4], fjz[4];
    #pragma unroll
    for (int k = 0; k < 4; ++k) {
        const float p0 = pj[k * 3 + 0];
        const float p1 = pj[k * 3 + 1];
        const float p2 = pj[k * 3 + 2];
        fjx[k] = p0 * i00 + p1 * i10 + p2 * i20;
        fjy[k] = p0 * i01 + p1 * i11 + p2 * i21;
        fjz[k] = p0 * i02 + p1 * i12 + p2 * i22;
    }

    const int4 ej4 = *reinterpret_cast<const int4*>(ent + base + j0);
    const bool ej[4] = { ej4.x != 0, ej4.y != 0, ej4.z != 0, ej4.w != 0 };

    const size_t NN       = (size_t)N * N;
    const size_t sod_off  = (size_t)B * NN * 3;
    const size_t mask_off = (size_t)B * NN * 4;

    #pragma unroll 1
    for (int t = 0; t < I_TILE; ++t) {
        const int i = i0 + t;
        float* buf = sbuf[t & 1][warp];

        // per-warp backpressure: this buffer's group committed at t-2
        if (t >= 2) {
            if (lane == 0)
                asm volatile("cp.async.bulk.wait_group.read 1;" ::: "memory");
            __syncwarp();
        }

        // i-side frac: broadcast loads + one mat-vec (cheap)
        const float q0 = pos[((size_t)base + i) * 3 + 0];
        const float q1 = pos[((size_t)base + i) * 3 + 1];
        const float q2 = pos[((size_t)base + i) * 3 + 2];
        const float fi0 = q0 * i00 + q1 * i10 + q2 * i20;
        const float fi1 = q0 * i01 + q1 * i11 + q2 * i21;
        const float fi2 = q0 * i02 + q1 * i12 + q2 * i22;
        const bool  ent_i = ent[base + i] != 0;

        float vx[4], vy[4], vz[4], sd[4], mk[4];

        #pragma unroll
        for (int k = 0; k < 4; ++k) {
            const int j = j0 + k;
            float d0 = fjx[k] - fi0;
            float d1 = fjy[k] - fi1;
            float d2 = fjz[k] - fi2;
            d0 -= rintf(d0) * pb0;   // round-half-even, matches jnp.round
            d1 -= rintf(d1) * pb1;
            d2 -= rintf(d2) * pb2;

            float v0 = d0 * c00 + d1 * c10 + d2 * c20;
            float v1 = d0 * c01 + d1 * c11 + d2 * c21;
            float v2 = d0 * c02 + d1 * c12 + d2 * c22;
            float s  = v0 * v0 + v1 * v1 + v2 * v2;

            // one select -> mask float; value-masking via FMUL (FMA pipe)
            const bool ok = ent_i && ej[k] && (i != j) && (s < RC2);
            const float m = ok ? 1.0f : 0.0f;   // exact 1.0/0.0
            vx[k] = v0 * m;
            vy[k] = v1 * m;
            vz[k] = v2 * m;
            sd[k] = s  * m;
            mk[k] = m;
        }

        // stage into warp-private SMEM slice (STS.128)
        float4* vdst = reinterpret_cast<float4*>(buf + lane * 12);
        vdst[0] = make_float4(vx[0], vy[0], vz[0], vx[1]);
        vdst[1] = make_float4(vy[1], vz[1], vx[2], vy[2]);
        vdst[2] = make_float4(vz[2], vx[3], vy[3], vz[3]);
        *reinterpret_cast<float4*>(buf + W_SOD + lane * 4) =
            make_float4(sd[0], sd[1], sd[2], sd[3]);
        *reinterpret_cast<float4*>(buf + W_MSK + lane * 4) =
            make_float4(mk[0], mk[1], mk[2], mk[3]);

        __syncwarp();

        if (lane == 0) {
            asm volatile("fence.proxy.async.shared::cta;" ::: "memory");
            const size_t pair = ((size_t)base + i) * N + jwb;
            bulk_store_ef(out + pair * 3,       smem_u32(buf),         WJ * 3 * 4, policy);
            bulk_store_ef(out + sod_off + pair, smem_u32(buf + W_SOD), WJ * 4,     policy);
            bulk_store_ef(out + mask_off + pair,smem_u32(buf + W_MSK), WJ * 4,     policy);
            asm volatile("cp.async.bulk.commit_group;" ::: "memory");
        }
        __syncwarp();
    }

    // SMEM must stay alive until this warp's TMA reads complete
    if (lane == 0)
        asm volatile("cp.async.bulk.wait_group.read 0;" ::: "memory");
    __syncwarp();
}

extern "C" void kernel_launch(void* const* d_in, const int* in_sizes, int n_in,
                              void* d_out, int out_size)
{
    const float* pos = (const float*)d_in[0];
    const float* cel = (const float*)d_in[1];
    const int*   pbc = (const int*)  d_in[2];
    const int*   ent = (const int*)  d_in[3];
    float* out = (float*)d_out;

    const int B = in_sizes[1] / 9;          // cel_mat has B*9 elements
    const int N = in_sizes[3] / B;          // ent has B*N elements

    dim3 threads(128, 1, 1);
    dim3 blocks(N / JBLK, N / I_TILE, B);
    pair_kernel<<<blocks, threads>>>(pos, cel, pbc, ent, out, N, B);
}